// round 3
// baseline (speedup 1.0000x reference)
#include <cuda_runtime.h>

typedef unsigned long long u64;

#define KBOX 1024
#define TILE 128
#define HDIM 128
#define HT_STRIDE 132

// smem layout (float offsets)
#define OFF_W1 0        // 13*128 = 1664
#define OFF_B1 1664     // 128
#define OFF_W2 1792     // 128*128 = 16384
#define OFF_B2 18176    // 128
#define OFF_HT 18304    // 128*132 = 16896
#define SMEM_FLOATS 35200
#define SMEM_BYTES (SMEM_FLOATS * 4)

// ---- packed f32x2 helpers (sm_100+; FFMA2 only reachable via PTX) ----
__device__ __forceinline__ u64 dup2(float x) {
    u64 r; asm("mov.b64 %0, {%1, %1};" : "=l"(r) : "f"(x)); return r;
}
__device__ __forceinline__ void upk2(u64 v, float& lo, float& hi) {
    asm("mov.b64 {%0, %1}, %2;" : "=f"(lo), "=f"(hi) : "l"(v));
}
__device__ __forceinline__ void fma2(u64& d, u64 a, u64 b) {
    asm("fma.rn.f32x2 %0, %1, %2, %0;" : "+l"(d) : "l"(a), "l"(b));
}

union F4U { float4 f; ulonglong2 u; };

extern "C" __global__ void __launch_bounds__(256, 1)
pair_mlp_kernel(const float* __restrict__ boxes,
                const float* __restrict__ W1, const float* __restrict__ b1,
                const float* __restrict__ W2, const float* __restrict__ b2,
                float* __restrict__ out)
{
    extern __shared__ float sm[];
    float* W1s = sm + OFF_W1;
    float* b1s = sm + OFF_B1;
    float* W2s = sm + OFF_W2;
    float* b2s = sm + OFF_B2;
    float* hTs = sm + OFF_HT;

    const int tid = threadIdx.x;
    const int bx  = blockIdx.x;
    const int i   = bx >> 3;          // box-i index (constant for the tile)
    const int j0  = (bx & 7) << 7;    // first box-j index of the tile

    // ---- cooperative weight load (float4, coalesced) ----
    {
        const float4* s1 = (const float4*)W1; float4* d1 = (float4*)W1s;
        #pragma unroll 2
        for (int t = tid; t < 416; t += 256) d1[t] = s1[t];
        const float4* s2 = (const float4*)W2; float4* d2 = (float4*)W2s;
        #pragma unroll 4
        for (int t = tid; t < 4096; t += 256) d2[t] = s2[t];
        if (tid < 32)       ((float4*)b1s)[tid]      = ((const float4*)b1)[tid];
        else if (tid < 64)  ((float4*)b2s)[tid - 32] = ((const float4*)b2)[tid - 32];
    }
    __syncthreads();

    // ---- phase 1: pair features + GEMM1 (13->128) + ReLU -> hT[k][m] ----
    {
        const int m    = tid & 127;   // tile row (pair index within tile)
        const int half = tid >> 7;    // which 64 output columns
        const int j    = j0 + m;

        const float4 Bi = ((const float4*)boxes)[i];
        const float4 Bj = ((const float4*)boxes)[j];
        const float xi = Bi.x, yi = Bi.y, wi = Bi.z, hi = Bi.w;
        const float xj = Bj.x, yj = Bj.y, wj = Bj.z, hj = Bj.w;

        const float rwi = 1.0f / wi, rhi = 1.0f / hi;
        const float dx = (xj - xi) * rwi;
        const float dy = (yj - yi) * rhi;
        const float dw = __logf(wj * rwi + 1e-6f);
        const float dh = __logf(hj * rhi + 1e-6f);
        const float iw = fmaxf(0.0f, fminf(xi + wi, xj + wj) - fmaxf(xi, xj));
        const float ih = fmaxf(0.0f, fminf(yi + hi, yj + hj) - fmaxf(yi, yj));
        const float inter = iw * ih;
        const float uni   = wi * hi + wj * hj - inter;
        const float iou   = inter / (uni + 1e-6f);

        u64 fd[13];
        fd[0]  = dup2(dx);  fd[1]  = dup2(dy);  fd[2]  = dup2(dw);  fd[3]  = dup2(dh);
        fd[4]  = dup2(wi);  fd[5]  = dup2(hi);  fd[6]  = dup2(wj);  fd[7]  = dup2(hj);
        fd[8]  = dup2(iou); fd[9]  = dup2(xi);  fd[10] = dup2(yi);  fd[11] = dup2(xj);
        fd[12] = dup2(yj);

        const int c0 = half << 6;
        #pragma unroll
        for (int c = 0; c < 64; c += 4) {
            F4U bv; bv.f = *(const float4*)&b1s[c0 + c];
            u64 a0 = bv.u.x, a1 = bv.u.y;
            #pragma unroll
            for (int t = 0; t < 13; t++) {
                F4U wv; wv.f = *(const float4*)&W1s[t * 128 + c0 + c];
                fma2(a0, fd[t], wv.u.x);
                fma2(a1, fd[t], wv.u.y);
            }
            float v0, v1, v2, v3;
            upk2(a0, v0, v1); upk2(a1, v2, v3);
            v0 = fmaxf(v0, 0.0f); v1 = fmaxf(v1, 0.0f);
            v2 = fmaxf(v2, 0.0f); v3 = fmaxf(v3, 0.0f);
            const int cc = c0 + c;
            hTs[(cc + 0) * HT_STRIDE + m] = v0;
            hTs[(cc + 1) * HT_STRIDE + m] = v1;
            hTs[(cc + 2) * HT_STRIDE + m] = v2;
            hTs[(cc + 3) * HT_STRIDE + m] = v3;
        }
    }
    __syncthreads();

    // ---- phase 2: GEMM2 (128x128x128) with packed f32x2 FMA ----
    {
        const int tx = tid & 15;
        const int ty = tid >> 4;
        const int n0 = tx << 3;       // output columns [n0, n0+8)
        const int m0 = ty << 3;       // tile rows     [m0, m0+8)

        u64 acc[8][4];
        #pragma unroll
        for (int a = 0; a < 8; a++)
            #pragma unroll
            for (int b = 0; b < 4; b++) acc[a][b] = 0ULL;

        const float* hp = hTs + m0;
        const float* wp = W2s + n0;

        #pragma unroll 4
        for (int k = 0; k < 128; k++) {
            F4U alo, ahi, blo, bhi;
            alo.f = *(const float4*)(hp + k * HT_STRIDE);
            ahi.f = *(const float4*)(hp + k * HT_STRIDE + 4);
            blo.f = *(const float4*)(wp + k * 128);
            bhi.f = *(const float4*)(wp + k * 128 + 4);

            const u64 bp0 = blo.u.x, bp1 = blo.u.y, bp2 = bhi.u.x, bp3 = bhi.u.y;

            u64 ad[8];
            ad[0] = dup2(alo.f.x); ad[1] = dup2(alo.f.y);
            ad[2] = dup2(alo.f.z); ad[3] = dup2(alo.f.w);
            ad[4] = dup2(ahi.f.x); ad[5] = dup2(ahi.f.y);
            ad[6] = dup2(ahi.f.z); ad[7] = dup2(ahi.f.w);

            #pragma unroll
            for (int mi = 0; mi < 8; mi++) {
                fma2(acc[mi][0], ad[mi], bp0);
                fma2(acc[mi][1], ad[mi], bp1);
                fma2(acc[mi][2], ad[mi], bp2);
                fma2(acc[mi][3], ad[mi], bp3);
            }
        }

        const float4 b2lo = *(const float4*)&b2s[n0];
        const float4 b2hi = *(const float4*)&b2s[n0 + 4];

        #pragma unroll
        for (int mi = 0; mi < 8; mi++) {
            const int j = j0 + m0 + mi;
            if (j == i) continue;                      // diagonal pair: no output row
            const int p = (i << 10) + j;               // full-matrix row index
            const int outrow = p - (p + 1024) / 1025;  // compact off-diagonal row
            float l0, h0, l1, h1, l2, h2, l3, h3;
            upk2(acc[mi][0], l0, h0); upk2(acc[mi][1], l1, h1);
            upk2(acc[mi][2], l2, h2); upk2(acc[mi][3], l3, h3);
            const float4 v0 = make_float4(l0 + b2lo.x, h0 + b2lo.y, l1 + b2lo.z, h1 + b2lo.w);
            const float4 v1 = make_float4(l2 + b2hi.x, h2 + b2hi.y, l3 + b2hi.z, h3 + b2hi.w);
            float4* dst = (float4*)(out + (size_t)outrow * HDIM + n0);
            dst[0] = v0;
            dst[1] = v1;
        }
    }
}

extern "C" void kernel_launch(void* const* d_in, const int* in_sizes, int n_in,
                              void* d_out, int out_size)
{
    const float* boxes = (const float*)d_in[0];
    const float* W1    = (const float*)d_in[1];
    const float* b1    = (const float*)d_in[2];
    const float* W2    = (const float*)d_in[3];
    const float* b2    = (const float*)d_in[4];
    float* out = (float*)d_out;

    cudaFuncSetAttribute(pair_mlp_kernel,
                         cudaFuncAttributeMaxDynamicSharedMemorySize, SMEM_BYTES);

    // 8192 tiles of 128 pair-rows each (i constant per tile)
    pair_mlp_kernel<<<(KBOX / TILE) * KBOX, 256, SMEM_BYTES>>>(boxes, W1, b1, W2, b2, out);
}

// round 5
// speedup vs baseline: 2.1009x; 2.1009x over previous
#include <cuda_runtime.h>
#include <cuda_fp16.h>
#include <cstring>

typedef unsigned long long u64;
typedef unsigned int u32;

#define KBOX   1024
#define NTILES 8192
#define GRID   296
#define BP_STRIDE 136   // u32 stride per k-pair row (512B + 32B pad -> conflict-free)

// ---- packed f32x2 helpers ----
__device__ __forceinline__ u64 dup2(float x) {
    u64 r; asm("mov.b64 %0, {%1, %1};" : "=l"(r) : "f"(x)); return r;
}
__device__ __forceinline__ void upk2(u64 v, float& lo, float& hi) {
    asm("mov.b64 {%0, %1}, %2;" : "=f"(lo), "=f"(hi) : "l"(v));
}
__device__ __forceinline__ void fma2(u64& d, u64 a, u64 b) {
    asm("fma.rn.f32x2 %0, %1, %2, %0;" : "+l"(d) : "l"(a), "l"(b));
}

__device__ __forceinline__ u32 h2u(__half2 h) {
    u32 u; memcpy(&u, &h, 4); return u;
}

// m16n8k16 fp16 MMA, fp32 accum
__device__ __forceinline__ void mma16816(float* c, u32 a0, u32 a1, u32 a2, u32 a3,
                                         u32 b0, u32 b1) {
    asm volatile(
        "mma.sync.aligned.m16n8k16.row.col.f32.f16.f16.f32 "
        "{%0,%1,%2,%3}, {%4,%5,%6,%7}, {%8,%9}, {%0,%1,%2,%3};"
        : "+f"(c[0]), "+f"(c[1]), "+f"(c[2]), "+f"(c[3])
        : "r"(a0), "r"(a1), "r"(a2), "r"(a3), "r"(b0), "r"(b1));
}

// 13 pair features for (box i, box j), duplicated into f32x2 lanes
__device__ __forceinline__ void feat13(u64* fd, const float4& Bi, const float4& Bj) {
    const float xi = Bi.x, yi = Bi.y, wi = Bi.z, hi_ = Bi.w;
    const float xj = Bj.x, yj = Bj.y, wj = Bj.z, hj = Bj.w;
    const float rwi = 1.0f / wi, rhi = 1.0f / hi_;
    const float dx = (xj - xi) * rwi;
    const float dy = (yj - yi) * rhi;
    const float dw = __logf(wj * rwi + 1e-6f);
    const float dh = __logf(hj * rhi + 1e-6f);
    const float iw = fmaxf(0.0f, fminf(xi + wi, xj + wj) - fmaxf(xi, xj));
    const float ih = fmaxf(0.0f, fminf(yi + hi_, yj + hj) - fmaxf(yi, yj));
    const float inter = iw * ih;
    const float uni   = wi * hi_ + wj * hj - inter;
    const float iou   = inter / (uni + 1e-6f);
    fd[0]=dup2(dx);  fd[1]=dup2(dy);  fd[2]=dup2(dw);  fd[3]=dup2(dh);
    fd[4]=dup2(wi);  fd[5]=dup2(hi_); fd[6]=dup2(wj);  fd[7]=dup2(hj);
    fd[8]=dup2(iou); fd[9]=dup2(xi);  fd[10]=dup2(yi); fd[11]=dup2(xj);
    fd[12]=dup2(yj);
}

extern "C" __global__ void __launch_bounds__(256, 2)
pair_mlp_hmma(const float* __restrict__ boxes,
              const float* __restrict__ W1, const float* __restrict__ b1,
              const float* __restrict__ W2, const float* __restrict__ b2,
              float* __restrict__ out)
{
    __shared__ u32   Bp[64 * BP_STRIDE];  // fp16x2-packed W2: Bp[kp][n] = {W2[2kp][n], W2[2kp+1][n]}
    __shared__ float W1s[13 * 128];
    __shared__ float b1s[128];
    __shared__ float b2s[128];

    const int tid = threadIdx.x;
    const int w   = tid >> 5;
    const int l   = tid & 31;

    // ---- one-time setup ----
    for (int idx = tid; idx < 64 * 128; idx += 256) {
        const int kp = idx >> 7, n = idx & 127;
        const __half2 p = __floats2half2_rn(W2[(2 * kp) * 128 + n],
                                            W2[(2 * kp + 1) * 128 + n]);
        Bp[kp * BP_STRIDE + n] = h2u(p);
    }
    for (int idx = tid; idx < 13 * 128; idx += 256) W1s[idx] = W1[idx];
    if (tid < 128) { b1s[tid] = b1[tid]; b2s[tid] = b2[tid]; }
    __syncthreads();

    const int r0 = (w << 4) + (l >> 2);   // tile row for a0/a2 (r1 = r0 + 8 for a1/a3)
    const int lp = l & 3;                  // fragment col group

    for (int t = blockIdx.x; t < NTILES; t += GRID) {
        const int i  = t >> 3;
        const int j0 = (t & 7) << 7;
        const int jA = j0 + r0;
        const int jB = jA + 8;

        // ---- phase 1: features + GEMM1 (13->128) fp32 + ReLU -> fp16 hi/lo A-fragments ----
        u32 hhiA[16], hloA[16], hhiB[16], hloB[16];
        {
            const float4 Bi = __ldg((const float4*)boxes + i);
            const float4 BjA = __ldg((const float4*)boxes + jA);
            const float4 BjB = __ldg((const float4*)boxes + jB);
            u64 fdA[13], fdB[13];
            feat13(fdA, Bi, BjA);
            feat13(fdB, Bi, BjB);

            #pragma unroll
            for (int g = 0; g < 16; g++) {
                const int p = 4 * g + lp;          // h col-pair index (cols 2p, 2p+1)
                u64 accA = *(const u64*)&b1s[2 * p];
                u64 accB = accA;
                #pragma unroll
                for (int tt = 0; tt < 13; tt++) {
                    const u64 wv = *(const u64*)&W1s[tt * 128 + 2 * p];
                    fma2(accA, fdA[tt], wv);
                    fma2(accB, fdB[tt], wv);
                }
                float vl, vh;
                upk2(accA, vl, vh);
                vl = fmaxf(vl, 0.0f); vh = fmaxf(vh, 0.0f);
                __half2 hh = __floats2half2_rn(vl, vh);
                float2 hf  = __half22float2(hh);
                __half2 ll = __floats2half2_rn(vl - hf.x, vh - hf.y);
                hhiA[g] = h2u(hh); hloA[g] = h2u(ll);

                upk2(accB, vl, vh);
                vl = fmaxf(vl, 0.0f); vh = fmaxf(vh, 0.0f);
                hh = __floats2half2_rn(vl, vh);
                hf = __half22float2(hh);
                ll = __floats2half2_rn(vl - hf.x, vh - hf.y);
                hhiB[g] = h2u(hh); hloB[g] = h2u(ll);
            }
        }

        // output rows / masks
        const bool okA = (jA != i), okB = (jB != i);
        const int pA = (i << 10) + jA;
        const int pB = (i << 10) + jB;
        float* dA = out + (size_t)(pA - (pA + 1024) / 1025) * 128;
        float* dB = out + (size_t)(pB - (pB + 1024) / 1025) * 128;

        // ---- phase 2: GEMM2 via HMMA, 2 passes of 64 cols ----
        #pragma unroll
        for (int pass = 0; pass < 2; pass++) {
            float acc[8][4];
            #pragma unroll
            for (int nt = 0; nt < 8; nt++) {
                acc[nt][0] = 0.f; acc[nt][1] = 0.f; acc[nt][2] = 0.f; acc[nt][3] = 0.f;
            }

            // per-thread B base: row kp = lp, col n = pass*64 + l/4
            const u32* bbase = Bp + lp * BP_STRIDE + pass * 64 + (l >> 2);

            #pragma unroll
            for (int kt = 0; kt < 8; kt++) {
                const u32 ah0 = hhiA[2 * kt],     ah1 = hhiB[2 * kt];
                const u32 ah2 = hhiA[2 * kt + 1], ah3 = hhiB[2 * kt + 1];
                const u32 al0 = hloA[2 * kt],     al1 = hloB[2 * kt];
                const u32 al2 = hloA[2 * kt + 1], al3 = hloB[2 * kt + 1];
                const u32* bk = bbase + (8 * kt) * BP_STRIDE;
                #pragma unroll
                for (int nt = 0; nt < 8; nt++) {
                    const u32 bv0 = bk[nt * 8];                   // kp = 8kt+lp
                    const u32 bv1 = bk[4 * BP_STRIDE + nt * 8];   // kp = 8kt+4+lp
                    mma16816(acc[nt], ah0, ah1, ah2, ah3, bv0, bv1);
                    mma16816(acc[nt], al0, al1, al2, al3, bv0, bv1);
                }
            }

            // epilogue for this pass
            #pragma unroll
            for (int nt = 0; nt < 8; nt++) {
                const int n = pass * 64 + nt * 8 + lp * 2;
                const float2 bb = *(const float2*)&b2s[n];
                if (okA) {
                    float2 v = make_float2(acc[nt][0] + bb.x, acc[nt][1] + bb.y);
                    *(float2*)(dA + n) = v;
                }
                if (okB) {
                    float2 v = make_float2(acc[nt][2] + bb.x, acc[nt][3] + bb.y);
                    *(float2*)(dB + n) = v;
                }
            }
        }
    }
}

extern "C" void kernel_launch(void* const* d_in, const int* in_sizes, int n_in,
                              void* d_out, int out_size)
{
    const float* boxes = (const float*)d_in[0];
    const float* W1    = (const float*)d_in[1];
    const float* b1    = (const float*)d_in[2];
    const float* W2    = (const float*)d_in[3];
    const float* b2    = (const float*)d_in[4];
    float* out = (float*)d_out;

    pair_mlp_hmma<<<GRID, 256>>>(boxes, W1, b1, W2, b2, out);
}

// round 7
// speedup vs baseline: 2.3538x; 1.1204x over previous
#include <cuda_runtime.h>
#include <cuda_fp16.h>
#include <cstring>

typedef unsigned long long u64;
typedef unsigned int u32;

#define KBOX   1024
#define NT2    4096          // 4096 tiles of 256 rows
#define GRID   296
#define BF_STRIDE 260        // u32 per combo (64 chunks + 1 pad chunk)

// ---- packed f32x2 helpers ----
__device__ __forceinline__ u64 dup2(float x) {
    u64 r; asm("mov.b64 %0, {%1, %1};" : "=l"(r) : "f"(x)); return r;
}
__device__ __forceinline__ void upk2(u64 v, float& lo, float& hi) {
    asm("mov.b64 {%0, %1}, %2;" : "=f"(lo), "=f"(hi) : "l"(v));
}
__device__ __forceinline__ void fma2(u64& d, u64 a, u64 b) {
    asm("fma.rn.f32x2 %0, %1, %2, %0;" : "+l"(d) : "l"(a), "l"(b));
}
__device__ __forceinline__ u32 h2u(__half2 h) {
    u32 u; memcpy(&u, &h, 4); return u;
}

// m16n8k16 fp16 MMA, fp32 accum
__device__ __forceinline__ void mma16816(float* c, u32 a0, u32 a1, u32 a2, u32 a3,
                                         u32 b0, u32 b1) {
    asm volatile(
        "mma.sync.aligned.m16n8k16.row.col.f32.f16.f16.f32 "
        "{%0,%1,%2,%3}, {%4,%5,%6,%7}, {%8,%9}, {%0,%1,%2,%3};"
        : "+f"(c[0]), "+f"(c[1]), "+f"(c[2]), "+f"(c[3])
        : "r"(a0), "r"(a1), "r"(a2), "r"(a3), "r"(b0), "r"(b1));
}

// 13 pair features for (box i, box j), duplicated into f32x2 lanes
__device__ __forceinline__ void feat13(u64* fd, const float4& Bi, const float4& Bj) {
    const float xi = Bi.x, yi = Bi.y, wi = Bi.z, hi_ = Bi.w;
    const float xj = Bj.x, yj = Bj.y, wj = Bj.z, hj = Bj.w;
    const float rwi = 1.0f / wi, rhi = 1.0f / hi_;
    const float dx = (xj - xi) * rwi;
    const float dy = (yj - yi) * rhi;
    const float dw = __logf(wj * rwi + 1e-6f);
    const float dh = __logf(hj * rhi + 1e-6f);
    const float iw = fmaxf(0.0f, fminf(xi + wi, xj + wj) - fmaxf(xi, xj));
    const float ih = fmaxf(0.0f, fminf(yi + hi_, yj + hj) - fmaxf(yi, yj));
    const float inter = iw * ih;
    const float uni   = wi * hi_ + wj * hj - inter;
    const float iou   = inter / (uni + 1e-6f);
    fd[0]=dup2(dx);  fd[1]=dup2(dy);  fd[2]=dup2(dw);  fd[3]=dup2(dh);
    fd[4]=dup2(wi);  fd[5]=dup2(hi_); fd[6]=dup2(wj);  fd[7]=dup2(hj);
    fd[8]=dup2(iou); fd[9]=dup2(xi);  fd[10]=dup2(yi); fd[11]=dup2(xj);
    fd[12]=dup2(yj);
}

extern "C" __global__ void __launch_bounds__(256, 2)
pair_mlp_hmma2(const float* __restrict__ boxes,
               const float* __restrict__ W1, const float* __restrict__ b1,
               const float* __restrict__ W2, const float* __restrict__ b2,
               float* __restrict__ out)
{
    // Fragment-ordered W2 (fp16x2 packed), per (npos,lp) combo; conflict-free LDS.128
    __shared__ u32   Bf[32 * BF_STRIDE];   // 33280 B
    __shared__ float W1s[13 * 128];
    __shared__ float b1s[128];
    __shared__ float b2s[128];

    const int tid = threadIdx.x;
    const int w   = tid >> 5;
    const int l   = tid & 31;
    const int lp  = l & 3;           // k-pair group within fragment
    const int npos = l >> 2;         // n position within fragment
    const int combo2 = npos * 4 + lp;

    // ---- one-time setup ----
    // Bf[combo2*260 + (pass*8+kt)*8 + c*4 + wd]:
    //   c=0: bv0 for nt=wd (kp = 8kt+lp),  c=1: bv1 (kp = 8kt+4+lp)
    //   n = pass*32 + wd*8 + npos
    for (int idx = tid; idx < 8192; idx += 256) {
        const int cb  = idx >> 8;          // combo 0..31
        const int rest = idx & 255;
        const int s2  = rest >> 3;         // pass*8+kt, 0..31
        const int q   = rest & 7;
        const int c   = q >> 2;
        const int wd  = q & 3;
        const int pass = s2 >> 3, kt = s2 & 7;
        const int lp_  = cb & 3,  np_ = cb >> 2;
        const int kp  = 8 * kt + lp_ + 4 * c;
        const int n   = pass * 32 + wd * 8 + np_;
        const __half2 p = __floats2half2_rn(W2[(2 * kp) * 128 + n],
                                            W2[(2 * kp + 1) * 128 + n]);
        Bf[cb * BF_STRIDE + s2 * 8 + q] = h2u(p);
    }
    for (int idx = tid; idx < 13 * 128; idx += 256) W1s[idx] = W1[idx];
    if (tid < 128) { b1s[tid] = b1[tid]; b2s[tid] = b2[tid]; }
    __syncthreads();

    const u32* bcombo = Bf + combo2 * BF_STRIDE;

    for (int t = blockIdx.x; t < NT2; t += GRID) {
        const int i  = t >> 2;
        const int j0 = (t & 3) << 8;            // 256-row tile
        const int jbase = j0 + w * 32 + npos;   // this thread's base row

        // ---- phase 1: features + GEMM1 fp32 + ReLU -> fp16 A-fragments, 4 rows ----
        u32 hL[2][16], hH[2][16];               // [set][col-group]; rows: jbase+16s (+8)
        const float4 Bi = __ldg((const float4*)boxes + i);
        #pragma unroll
        for (int s = 0; s < 2; s++) {
            const int jl = jbase + 16 * s;
            const float4 BjL = __ldg((const float4*)boxes + jl);
            const float4 BjH = __ldg((const float4*)boxes + jl + 8);
            u64 fdL[13], fdH[13];
            feat13(fdL, Bi, BjL);
            feat13(fdH, Bi, BjH);
            #pragma unroll
            for (int g = 0; g < 16; g++) {
                const int p = 4 * g + lp;       // h col-pair (cols 2p, 2p+1)
                u64 aL = *(const u64*)&b1s[2 * p];
                u64 aH = aL;
                #pragma unroll
                for (int tt = 0; tt < 13; tt++) {
                    const u64 wv = *(const u64*)&W1s[tt * 128 + 2 * p];
                    fma2(aL, fdL[tt], wv);
                    fma2(aH, fdH[tt], wv);
                }
                float vl, vh;
                upk2(aL, vl, vh);
                vl = fmaxf(vl, 0.0f); vh = fmaxf(vh, 0.0f);
                hL[s][g] = h2u(__floats2half2_rn(vl, vh));
                upk2(aH, vl, vh);
                vl = fmaxf(vl, 0.0f); vh = fmaxf(vh, 0.0f);
                hH[s][g] = h2u(__floats2half2_rn(vl, vh));
            }
        }

        // ---- output row pointers (compacted off-diagonal), 4 rows ----
        bool   ok[4];
        float* dst[4];
        #pragma unroll
        for (int r = 0; r < 4; r++) {
            const int j = jbase + r * 8;
            ok[r] = (j != i);
            const int p = (i << 10) + j;
            dst[r] = out + (size_t)(p - (p + 1024) / 1025) * 128;
        }

        // ---- phase 2: GEMM2 via HMMA, 4 passes of 32 cols ----
        #pragma unroll
        for (int pass = 0; pass < 4; pass++) {
            float acc[2][4][4];
            #pragma unroll
            for (int s = 0; s < 2; s++)
                #pragma unroll
                for (int nt = 0; nt < 4; nt++) {
                    acc[s][nt][0] = 0.f; acc[s][nt][1] = 0.f;
                    acc[s][nt][2] = 0.f; acc[s][nt][3] = 0.f;
                }

            const u32* bp = bcombo + pass * 64;
            #pragma unroll
            for (int kt = 0; kt < 8; kt++) {
                const uint4 q0 = *(const uint4*)(bp + kt * 8);      // bv0 nt=0..3
                const uint4 q1 = *(const uint4*)(bp + kt * 8 + 4);  // bv1 nt=0..3
                #pragma unroll
                for (int s = 0; s < 2; s++) {
                    const u32 a0 = hL[s][2 * kt],     a1 = hH[s][2 * kt];
                    const u32 a2 = hL[s][2 * kt + 1], a3 = hH[s][2 * kt + 1];
                    mma16816(acc[s][0], a0, a1, a2, a3, q0.x, q1.x);
                    mma16816(acc[s][1], a0, a1, a2, a3, q0.y, q1.y);
                    mma16816(acc[s][2], a0, a1, a2, a3, q0.z, q1.z);
                    mma16816(acc[s][3], a0, a1, a2, a3, q0.w, q1.w);
                }
            }

            // epilogue for this pass
            #pragma unroll
            for (int s = 0; s < 2; s++)
                #pragma unroll
                for (int nt = 0; nt < 4; nt++) {
                    const int n = pass * 32 + nt * 8 + lp * 2;
                    const float2 bb = *(const float2*)&b2s[n];
                    const int rL = s * 2, rH = s * 2 + 1;
                    if (ok[rL]) {
                        float2 v = make_float2(acc[s][nt][0] + bb.x,
                                               acc[s][nt][1] + bb.y);
                        *(float2*)(dst[rL] + n) = v;
                    }
                    if (ok[rH]) {
                        float2 v = make_float2(acc[s][nt][2] + bb.x,
                                               acc[s][nt][3] + bb.y);
                        *(float2*)(dst[rH] + n) = v;
                    }
                }
        }
    }
}

extern "C" void kernel_launch(void* const* d_in, const int* in_sizes, int n_in,
                              void* d_out, int out_size)
{
    const float* boxes = (const float*)d_in[0];
    const float* W1    = (const float*)d_in[1];
    const float* b1    = (const float*)d_in[2];
    const float* W2    = (const float*)d_in[3];
    const float* b2    = (const float*)d_in[4];
    float* out = (float*)d_out;

    pair_mlp_hmma2<<<GRID, 256>>>(boxes, W1, b1, W2, b2, out);
}

// round 10
// speedup vs baseline: 4.2753x; 1.8163x over previous
#include <cuda_runtime.h>
#include <cuda_fp16.h>
#include <cstring>

typedef unsigned long long u64;
typedef unsigned int u32;

#define KBOX   1024
#define NT2    4096          // 4096 tiles of 256 rows
#define GRID   296
#define BF_STRIDE 260        // u32 per combo (64 chunks + 1 pad chunk)

__device__ __forceinline__ u32 h2u(__half2 h) {
    u32 u; memcpy(&u, &h, 4); return u;
}

// m16n8k16 fp16 MMA, fp32 accum
__device__ __forceinline__ void mma16816(float* c, u32 a0, u32 a1, u32 a2, u32 a3,
                                         u32 b0, u32 b1) {
    asm volatile(
        "mma.sync.aligned.m16n8k16.row.col.f32.f16.f16.f32 "
        "{%0,%1,%2,%3}, {%4,%5,%6,%7}, {%8,%9}, {%0,%1,%2,%3};"
        : "+f"(c[0]), "+f"(c[1]), "+f"(c[2]), "+f"(c[3])
        : "r"(a0), "r"(a1), "r"(a2), "r"(a3), "r"(b0), "r"(b1));
}

// 13 pair features for (box i, box j); select this lane's 4 A-fragment k-slots
// (k = 2lp,2lp+1 and 2lp+8,2lp+9; feats[13]=1 bias slot, 14/15 = 0),
// split fp16 hi/lo and pack.
__device__ __forceinline__ void featfrag(const float4& Bi, const float4& Bj, int lp,
                                         u32& h0, u32& l0, u32& h1, u32& l1) {
    const float xi = Bi.x, yi = Bi.y, wi = Bi.z, hi_ = Bi.w;
    const float xj = Bj.x, yj = Bj.y, wj = Bj.z, hj = Bj.w;
    const float rwi = 1.0f / wi, rhi = 1.0f / hi_;
    const float dx = (xj - xi) * rwi;
    const float dy = (yj - yi) * rhi;
    const float dw = __logf(wj * rwi + 1e-6f);
    const float dh = __logf(hj * rhi + 1e-6f);
    const float iw = fmaxf(0.0f, fminf(xi + wi, xj + wj) - fmaxf(xi, xj));
    const float ih = fmaxf(0.0f, fminf(yi + hi_, yj + hj) - fmaxf(yi, yj));
    const float inter = iw * ih;
    const float uni   = wi * hi_ + wj * hj - inter;
    const float iou   = inter / (uni + 1e-6f);

    // pair0: k=2lp,2lp+1   pair1: k=2lp+8,2lp+9
    float p0x, p0y, p1x, p1y;
    if      (lp == 0) { p0x = dx; p0y = dy; p1x = iou;  p1y = xi;   }
    else if (lp == 1) { p0x = dw; p0y = dh; p1x = yi;   p1y = xj;   }
    else if (lp == 2) { p0x = wi; p0y = hi_; p1x = yj;  p1y = 1.0f; }
    else              { p0x = wj; p0y = hj; p1x = 0.0f; p1y = 0.0f; }

    __half2 a = __floats2half2_rn(p0x, p0y);
    float2 af = __half22float2(a);
    h0 = h2u(a);
    l0 = h2u(__floats2half2_rn(p0x - af.x, p0y - af.y));
    a = __floats2half2_rn(p1x, p1y);
    af = __half22float2(a);
    h1 = h2u(a);
    l1 = h2u(__floats2half2_rn(p1x - af.x, p1y - af.y));
}

extern "C" __global__ void __launch_bounds__(256, 2)
pair_mlp_hmma3(const float* __restrict__ boxes,
               const float* __restrict__ W1, const float* __restrict__ b1,
               const float* __restrict__ W2, const float* __restrict__ b2,
               float* __restrict__ out)
{
    // Fragment-ordered W2 (fp16x2 packed), per (npos,lp) combo; conflict-free LDS.128
    __shared__ u32   Bf[32 * BF_STRIDE];   // 33280 B
    // Fragment-ordered W1 (fp16x2), B-frags of m16n8k16 per ntile g: [g][lane][2]
    __shared__ u32   W1f[16 * 64];         // 4096 B
    __shared__ float b2s[128];

    const int tid = threadIdx.x;
    const int w   = tid >> 5;
    const int l   = tid & 31;
    const int lp  = l & 3;           // k-pair group within fragment
    const int npos = l >> 2;         // n position within fragment
    const int combo2 = npos * 4 + lp;

    // ---- one-time setup ----
    // W2 fragment pack (unchanged from R6)
    for (int idx = tid; idx < 8192; idx += 256) {
        const int cb  = idx >> 8;
        const int rest = idx & 255;
        const int s2  = rest >> 3;
        const int q   = rest & 7;
        const int c   = q >> 2;
        const int wd  = q & 3;
        const int pass = s2 >> 3, kt = s2 & 7;
        const int lp_  = cb & 3,  np_ = cb >> 2;
        const int kp  = 8 * kt + lp_ + 4 * c;
        const int n   = pass * 32 + wd * 8 + np_;
        const __half2 p = __floats2half2_rn(W2[(2 * kp) * 128 + n],
                                            W2[(2 * kp + 1) * 128 + n]);
        Bf[cb * BF_STRIDE + s2 * 8 + q] = h2u(p);
    }
    // W1 fragment pack: W1e[k][n] with k=13 -> b1, k>=14 -> 0
    for (int idx = tid; idx < 16 * 64; idx += 256) {
        const int g  = idx >> 6;
        const int h  = idx & 63;
        const int ll = h >> 1;          // lane
        const int wh = h & 1;           // b0 / b1
        const int n  = 8 * g + (ll >> 2);
        const int k0 = 2 * (ll & 3) + 8 * wh;
        float v0, v1;
        v0 = (k0 < 13) ? W1[k0 * 128 + n] : ((k0 == 13) ? b1[n] : 0.0f);
        const int k1 = k0 + 1;
        v1 = (k1 < 13) ? W1[k1 * 128 + n] : ((k1 == 13) ? b1[n] : 0.0f);
        W1f[g * 64 + ll * 2 + wh] = h2u(__floats2half2_rn(v0, v1));
    }
    if (tid < 128) b2s[tid] = b2[tid];
    __syncthreads();

    const u32* bcombo = Bf + combo2 * BF_STRIDE;

    for (int t = blockIdx.x; t < NT2; t += GRID) {
        const int i  = t >> 2;
        const int j0 = (t & 3) << 8;            // 256-row tile
        const int jbase = j0 + w * 32 + npos;   // this thread's base row

        // ---- phase 1: features -> A-frags, GEMM1 on tensor cores, ReLU -> fp16 ----
        u32 hL[2][16], hH[2][16];
        const float4 Bi = __ldg((const float4*)boxes + i);
        #pragma unroll
        for (int s = 0; s < 2; s++) {
            const int jl = jbase + 16 * s;
            const float4 BjL = __ldg((const float4*)boxes + jl);
            const float4 BjH = __ldg((const float4*)boxes + jl + 8);
            // A-fragments: a0/a2 = row jl, a1/a3 = row jl+8 (hi and lo splits)
            u32 a0h, a0l, a2h, a2l, a1h, a1l, a3h, a3l;
            featfrag(Bi, BjL, lp, a0h, a0l, a2h, a2l);
            featfrag(Bi, BjH, lp, a1h, a1l, a3h, a3l);

            #pragma unroll
            for (int g = 0; g < 16; g++) {
                const u32* wf = &W1f[g * 64 + 2 * l];
                const u32 w0 = wf[0], w1 = wf[1];
                float c[4] = {0.f, 0.f, 0.f, 0.f};
                mma16816(c, a0h, a1h, a2h, a3h, w0, w1);
                mma16816(c, a0l, a1l, a2l, a3l, w0, w1);
                c[0] = fmaxf(c[0], 0.f); c[1] = fmaxf(c[1], 0.f);
                c[2] = fmaxf(c[2], 0.f); c[3] = fmaxf(c[3], 0.f);
                hL[s][g] = h2u(__floats2half2_rn(c[0], c[1]));   // row jl cols 8g+2lp,+1
                hH[s][g] = h2u(__floats2half2_rn(c[2], c[3]));   // row jl+8
            }
        }

        // ---- output row pointers (compacted off-diagonal), 4 rows ----
        bool   ok[4];
        float* dst[4];
        #pragma unroll
        for (int r = 0; r < 4; r++) {
            const int j = jbase + r * 8;
            ok[r] = (j != i);
            const int p = (i << 10) + j;
            dst[r] = out + (size_t)(p - (p + 1024) / 1025) * 128;
        }

        // ---- phase 2: GEMM2 via HMMA, 4 passes of 32 cols ----
        #pragma unroll
        for (int pass = 0; pass < 4; pass++) {
            float acc[2][4][4];
            #pragma unroll
            for (int s = 0; s < 2; s++)
                #pragma unroll
                for (int nt = 0; nt < 4; nt++) {
                    acc[s][nt][0] = 0.f; acc[s][nt][1] = 0.f;
                    acc[s][nt][2] = 0.f; acc[s][nt][3] = 0.f;
                }

            const u32* bp = bcombo + pass * 64;
            #pragma unroll
            for (int kt = 0; kt < 8; kt++) {
                const uint4 q0 = *(const uint4*)(bp + kt * 8);      // bv0 nt=0..3
                const uint4 q1 = *(const uint4*)(bp + kt * 8 + 4);  // bv1 nt=0..3
                #pragma unroll
                for (int s = 0; s < 2; s++) {
                    const u32 a0 = hL[s][2 * kt],     a1 = hH[s][2 * kt];
                    const u32 a2 = hL[s][2 * kt + 1], a3 = hH[s][2 * kt + 1];
                    mma16816(acc[s][0], a0, a1, a2, a3, q0.x, q1.x);
                    mma16816(acc[s][1], a0, a1, a2, a3, q0.y, q1.y);
                    mma16816(acc[s][2], a0, a1, a2, a3, q0.z, q1.z);
                    mma16816(acc[s][3], a0, a1, a2, a3, q0.w, q1.w);
                }
            }

            // epilogue for this pass
            #pragma unroll
            for (int s = 0; s < 2; s++)
                #pragma unroll
                for (int nt = 0; nt < 4; nt++) {
                    const int n = pass * 32 + nt * 8 + lp * 2;
                    const float2 bb = *(const float2*)&b2s[n];
                    const int rL = s * 2, rH = s * 2 + 1;
                    if (ok[rL]) {
                        float2 v = make_float2(acc[s][nt][0] + bb.x,
                                               acc[s][nt][1] + bb.y);
                        *(float2*)(dst[rL] + n) = v;
                    }
                    if (ok[rH]) {
                        float2 v = make_float2(acc[s][nt][2] + bb.x,
                                               acc[s][nt][3] + bb.y);
                        *(float2*)(dst[rH] + n) = v;
                    }
                }
        }
    }
}

extern "C" void kernel_launch(void* const* d_in, const int* in_sizes, int n_in,
                              void* d_out, int out_size)
{
    const float* boxes = (const float*)d_in[0];
    const float* W1    = (const float*)d_in[1];
    const float* b1    = (const float*)d_in[2];
    const float* W2    = (const float*)d_in[3];
    const float* b2    = (const float*)d_in[4];
    float* out = (float*)d_out;

    pair_mlp_hmma3<<<GRID, 256>>>(boxes, W1, b1, W2, b2, out);
}

// round 12
// speedup vs baseline: 5.1748x; 1.2104x over previous
#include <cuda_runtime.h>
#include <cuda_fp16.h>
#include <cstring>

typedef unsigned long long u64;
typedef unsigned int u32;

#define KBOX   1024
#define NT2    4096          // 4096 tiles of 256 rows
#define GRID   296
#define BF_STRIDE 260        // u32 per combo (64 chunks + 1 pad chunk)

// dynamic smem layout (bytes)
#define OFF_BF   0           // 32*260*4 = 33280
#define OFF_W1F  33280       // 4096
#define OFF_B2   37376       // 512
#define OFF_STG  37888       // 8 warps * 1280 floats * 4 = 40960
#define SMEM_BYTES 78848
#define STG_WARP 1280        // floats per warp buffer (32 rows * 40)
#define STG_ROW  40          // floats per staged row (conflict-free padding)

__device__ __forceinline__ u32 h2u(__half2 h) {
    u32 u; memcpy(&u, &h, 4); return u;
}

// m16n8k16 fp16 MMA, fp32 accum
__device__ __forceinline__ void mma16816(float* c, u32 a0, u32 a1, u32 a2, u32 a3,
                                         u32 b0, u32 b1) {
    asm volatile(
        "mma.sync.aligned.m16n8k16.row.col.f32.f16.f16.f32 "
        "{%0,%1,%2,%3}, {%4,%5,%6,%7}, {%8,%9}, {%0,%1,%2,%3};"
        : "+f"(c[0]), "+f"(c[1]), "+f"(c[2]), "+f"(c[3])
        : "r"(a0), "r"(a1), "r"(a2), "r"(a3), "r"(b0), "r"(b1));
}

// 13 pair features for (box i, box j); select this lane's 4 A-fragment k-slots
// (k = 2lp,2lp+1 and 2lp+8,2lp+9; feats[13]=1 bias slot, 14/15 = 0),
// split fp16 hi/lo and pack.
__device__ __forceinline__ void featfrag(const float4& Bi, const float4& Bj, int lp,
                                         u32& h0, u32& l0, u32& h1, u32& l1) {
    const float xi = Bi.x, yi = Bi.y, wi = Bi.z, hi_ = Bi.w;
    const float xj = Bj.x, yj = Bj.y, wj = Bj.z, hj = Bj.w;
    const float rwi = 1.0f / wi, rhi = 1.0f / hi_;
    const float dx = (xj - xi) * rwi;
    const float dy = (yj - yi) * rhi;
    const float dw = __logf(wj * rwi + 1e-6f);
    const float dh = __logf(hj * rhi + 1e-6f);
    const float iw = fmaxf(0.0f, fminf(xi + wi, xj + wj) - fmaxf(xi, xj));
    const float ih = fmaxf(0.0f, fminf(yi + hi_, yj + hj) - fmaxf(yi, yj));
    const float inter = iw * ih;
    const float uni   = wi * hi_ + wj * hj - inter;
    const float iou   = inter / (uni + 1e-6f);

    // pair0: k=2lp,2lp+1   pair1: k=2lp+8,2lp+9
    float p0x, p0y, p1x, p1y;
    if      (lp == 0) { p0x = dx; p0y = dy; p1x = iou;  p1y = xi;   }
    else if (lp == 1) { p0x = dw; p0y = dh; p1x = yi;   p1y = xj;   }
    else if (lp == 2) { p0x = wi; p0y = hi_; p1x = yj;  p1y = 1.0f; }
    else              { p0x = wj; p0y = hj; p1x = 0.0f; p1y = 0.0f; }

    __half2 a = __floats2half2_rn(p0x, p0y);
    float2 af = __half22float2(a);
    h0 = h2u(a);
    l0 = h2u(__floats2half2_rn(p0x - af.x, p0y - af.y));
    a = __floats2half2_rn(p1x, p1y);
    af = __half22float2(a);
    h1 = h2u(a);
    l1 = h2u(__floats2half2_rn(p1x - af.x, p1y - af.y));
}

extern "C" __global__ void __launch_bounds__(256, 2)
pair_mlp_hmma4(const float* __restrict__ boxes,
               const float* __restrict__ W1, const float* __restrict__ b1,
               const float* __restrict__ W2, const float* __restrict__ b2,
               float* __restrict__ out)
{
    extern __shared__ char smemraw[];
    u32*   Bf  = (u32*)(smemraw + OFF_BF);    // fragment-ordered W2
    u32*   W1f = (u32*)(smemraw + OFF_W1F);   // fragment-ordered W1 (+bias row)
    float* b2s = (float*)(smemraw + OFF_B2);
    float* stgbuf = (float*)(smemraw + OFF_STG);

    const int tid = threadIdx.x;
    const int w   = tid >> 5;
    const int l   = tid & 31;
    const int lp  = l & 3;           // k-pair group within fragment
    const int npos = l >> 2;         // n position within fragment
    const int combo2 = npos * 4 + lp;

    // ---- one-time setup ----
    for (int idx = tid; idx < 8192; idx += 256) {
        const int cb  = idx >> 8;
        const int rest = idx & 255;
        const int s2  = rest >> 3;
        const int q   = rest & 7;
        const int c   = q >> 2;
        const int wd  = q & 3;
        const int pass = s2 >> 3, kt = s2 & 7;
        const int lp_  = cb & 3,  np_ = cb >> 2;
        const int kp  = 8 * kt + lp_ + 4 * c;
        const int n   = pass * 32 + wd * 8 + np_;
        const __half2 p = __floats2half2_rn(W2[(2 * kp) * 128 + n],
                                            W2[(2 * kp + 1) * 128 + n]);
        Bf[cb * BF_STRIDE + s2 * 8 + q] = h2u(p);
    }
    // W1 fragment pack: W1e[k][n] with k=13 -> b1, k>=14 -> 0
    for (int idx = tid; idx < 16 * 64; idx += 256) {
        const int g  = idx >> 6;
        const int h  = idx & 63;
        const int ll = h >> 1;          // lane
        const int wh = h & 1;           // b0 / b1
        const int n  = 8 * g + (ll >> 2);
        const int k0 = 2 * (ll & 3) + 8 * wh;
        float v0, v1;
        v0 = (k0 < 13) ? W1[k0 * 128 + n] : ((k0 == 13) ? b1[n] : 0.0f);
        const int k1 = k0 + 1;
        v1 = (k1 < 13) ? W1[k1 * 128 + n] : ((k1 == 13) ? b1[n] : 0.0f);
        W1f[g * 64 + ll * 2 + wh] = h2u(__floats2half2_rn(v0, v1));
    }
    if (tid < 128) b2s[tid] = b2[tid];
    __syncthreads();

    const u32* bcombo = Bf + combo2 * BF_STRIDE;
    float* mybuf = stgbuf + w * STG_WARP;
    const int colblk = (l & 7) * 4;     // epilogue drain column block
    const int rsub   = l >> 3;          // epilogue drain row sub-index

    for (int t = blockIdx.x; t < NT2; t += GRID) {
        const int i  = t >> 2;
        const int j0 = (t & 3) << 8;            // 256-row tile
        const int jwarp = j0 + w * 32;          // warp's first row
        const int jbase = jwarp + npos;         // this thread's base row

        // ---- phase 1: features -> A-frags, GEMM1 on tensor cores, ReLU -> fp16 ----
        u32 hL[2][16], hH[2][16];
        const float4 Bi = __ldg((const float4*)boxes + i);
        #pragma unroll
        for (int s = 0; s < 2; s++) {
            const int jl = jbase + 16 * s;
            const float4 BjL = __ldg((const float4*)boxes + jl);
            const float4 BjH = __ldg((const float4*)boxes + jl + 8);
            u32 a0h, a0l, a2h, a2l, a1h, a1l, a3h, a3l;
            featfrag(Bi, BjL, lp, a0h, a0l, a2h, a2l);
            featfrag(Bi, BjH, lp, a1h, a1l, a3h, a3l);

            #pragma unroll
            for (int g = 0; g < 16; g++) {
                const u32* wf = &W1f[g * 64 + 2 * l];
                const u32 w0 = wf[0], w1 = wf[1];
                float c[4] = {0.f, 0.f, 0.f, 0.f};
                mma16816(c, a0h, a1h, a2h, a3h, w0, w1);
                mma16816(c, a0l, a1l, a2l, a3l, w0, w1);
                c[0] = fmaxf(c[0], 0.f); c[1] = fmaxf(c[1], 0.f);
                c[2] = fmaxf(c[2], 0.f); c[3] = fmaxf(c[3], 0.f);
                hL[s][g] = h2u(__floats2half2_rn(c[0], c[1]));
                hH[s][g] = h2u(__floats2half2_rn(c[2], c[3]));
            }
        }

        // ---- phase 2: GEMM2 via HMMA, 4 passes of 32 cols; staged epilogue ----
        #pragma unroll
        for (int pass = 0; pass < 4; pass++) {
            float acc[2][4][4];
            #pragma unroll
            for (int s = 0; s < 2; s++)
                #pragma unroll
                for (int nt = 0; nt < 4; nt++) {
                    acc[s][nt][0] = 0.f; acc[s][nt][1] = 0.f;
                    acc[s][nt][2] = 0.f; acc[s][nt][3] = 0.f;
                }

            const u32* bp = bcombo + pass * 64;
            #pragma unroll
            for (int kt = 0; kt < 8; kt++) {
                const uint4 q0 = *(const uint4*)(bp + kt * 8);      // bv0 nt=0..3
                const uint4 q1 = *(const uint4*)(bp + kt * 8 + 4);  // bv1 nt=0..3
                #pragma unroll
                for (int s = 0; s < 2; s++) {
                    const u32 a0 = hL[s][2 * kt],     a1 = hH[s][2 * kt];
                    const u32 a2 = hL[s][2 * kt + 1], a3 = hH[s][2 * kt + 1];
                    mma16816(acc[s][0], a0, a1, a2, a3, q0.x, q1.x);
                    mma16816(acc[s][1], a0, a1, a2, a3, q0.y, q1.y);
                    mma16816(acc[s][2], a0, a1, a2, a3, q0.z, q1.z);
                    mma16816(acc[s][3], a0, a1, a2, a3, q0.w, q1.w);
                }
            }

            // stage: warp-private buffer, conflict-free STS.64 (row stride 40)
            #pragma unroll
            for (int s = 0; s < 2; s++)
                #pragma unroll
                for (int nt = 0; nt < 4; nt++) {
                    const int colo = nt * 8 + lp * 2;
                    float2 vL = make_float2(acc[s][nt][0], acc[s][nt][1]);
                    float2 vH = make_float2(acc[s][nt][2], acc[s][nt][3]);
                    *(float2*)&mybuf[((2 * s)     * 8 + npos) * STG_ROW + colo] = vL;
                    *(float2*)&mybuf[((2 * s + 1) * 8 + npos) * STG_ROW + colo] = vH;
                }
            __syncwarp();

            // drain: 8 x (LDS.128 + STG.128), each STG covers 4 full 128B lines
            const float4 bb = *(const float4*)&b2s[pass * 32 + colblk];
            #pragma unroll
            for (int tt = 0; tt < 8; tt++) {
                const int r = 4 * tt + rsub;
                float4 v = *(const float4*)&mybuf[r * STG_ROW + colblk];
                v.x += bb.x; v.y += bb.y; v.z += bb.z; v.w += bb.w;
                const int j = jwarp + r;
                if (j != i) {
                    const int outrow = i * 1023 + j - (j > i);
                    *(float4*)(out + (size_t)outrow * 128 + pass * 32 + colblk) = v;
                }
            }
            __syncwarp();
        }
    }
}

extern "C" void kernel_launch(void* const* d_in, const int* in_sizes, int n_in,
                              void* d_out, int out_size)
{
    const float* boxes = (const float*)d_in[0];
    const float* W1    = (const float*)d_in[1];
    const float* b1    = (const float*)d_in[2];
    const float* W2    = (const float*)d_in[3];
    const float* b2    = (const float*)d_in[4];
    float* out = (float*)d_out;

    cudaFuncSetAttribute(pair_mlp_hmma4,
                         cudaFuncAttributeMaxDynamicSharedMemorySize, SMEM_BYTES);
    pair_mlp_hmma4<<<GRID, 256, SMEM_BYTES>>>(boxes, W1, b1, W2, b2, out);
}

// round 13
// speedup vs baseline: 5.9793x; 1.1555x over previous
#include <cuda_runtime.h>
#include <cuda_fp16.h>
#include <cstring>

typedef unsigned long long u64;
typedef unsigned int u32;

#define KBOX   1024
#define NT2    4096          // 4096 tiles of 256 rows
#define GRID   296
#define BF_STRIDE 260        // u32 per combo (64 chunks + 1 pad chunk)

// dynamic smem layout (bytes)
#define OFF_BF   0           // 32*260*4 = 33280
#define OFF_W1F  33280       // 4096
#define OFF_B2   37376       // 512
#define OFF_STG  37888       // 8 warps * 1280 floats * 4 = 40960
#define SMEM_BYTES 78848
#define STG_WARP 1280        // floats per warp buffer (32 rows * 40)
#define STG_ROW  40          // floats per staged row (conflict-free padding)
#define FF_ROW   9           // u64 per feature row (7 pairs + pad, conflict-free)

__device__ __forceinline__ u32 h2u(__half2 h) {
    u32 u; memcpy(&u, &h, 4); return u;
}
__device__ __forceinline__ u32 hmax2z(u32 v) {
    __half2 h; memcpy(&h, &v, 4);
    h = __hmax2(h, __half2half2(__ushort_as_half(0)));
    return h2u(h);
}

// m16n8k16 fp16 MMA, fp32 accum
__device__ __forceinline__ void mma16816(float* c, u32 a0, u32 a1, u32 a2, u32 a3,
                                         u32 b0, u32 b1) {
    asm volatile(
        "mma.sync.aligned.m16n8k16.row.col.f32.f16.f16.f32 "
        "{%0,%1,%2,%3}, {%4,%5,%6,%7}, {%8,%9}, {%0,%1,%2,%3};"
        : "+f"(c[0]), "+f"(c[1]), "+f"(c[2]), "+f"(c[3])
        : "r"(a0), "r"(a1), "r"(a2), "r"(a3), "r"(b0), "r"(b1));
}

extern "C" __global__ void __launch_bounds__(256, 2)
pair_mlp_hmma5(const float* __restrict__ boxes,
               const float* __restrict__ W1, const float* __restrict__ b1,
               const float* __restrict__ W2, const float* __restrict__ b2,
               float* __restrict__ out)
{
    extern __shared__ char smemraw[];
    u32*   Bf   = (u32*)(smemraw + OFF_BF);    // fragment-ordered W2
    u32*   W1f2 = (u32*)(smemraw + OFF_W1F);   // pair-fragment-ordered W1 (+bias)
    float* b2s  = (float*)(smemraw + OFF_B2);
    float* stgbuf = (float*)(smemraw + OFF_STG);

    const int tid = threadIdx.x;
    const int w   = tid >> 5;
    const int l   = tid & 31;
    const int lp  = l & 3;           // k-pair group within fragment
    const int npos = l >> 2;         // n position within fragment
    const int combo2 = npos * 4 + lp;

    // ---- one-time setup ----
    // W2 fragment pack (unchanged)
    for (int idx = tid; idx < 8192; idx += 256) {
        const int cb  = idx >> 8;
        const int rest = idx & 255;
        const int s2  = rest >> 3;
        const int q   = rest & 7;
        const int c   = q >> 2;
        const int wd  = q & 3;
        const int pass = s2 >> 3, kt = s2 & 7;
        const int lp_  = cb & 3,  np_ = cb >> 2;
        const int kp  = 8 * kt + lp_ + 4 * c;
        const int n   = pass * 32 + wd * 8 + np_;
        const __half2 p = __floats2half2_rn(W2[(2 * kp) * 128 + n],
                                            W2[(2 * kp + 1) * 128 + n]);
        Bf[cb * BF_STRIDE + s2 * 8 + q] = h2u(p);
    }
    // W1 pack for LDS.128: [gp][lane][4] = {g=2gp:b0,b1, g=2gp+1:b0,b1}
    for (int idx = tid; idx < 1024; idx += 256) {
        const int gp = idx >> 7;
        const int rest = idx & 127;
        const int ll = rest >> 2;
        const int q  = rest & 3;
        const int g  = 2 * gp + (q >> 1);
        const int wh = q & 1;
        const int n  = 8 * g + (ll >> 2);
        const int k0 = 2 * (ll & 3) + 8 * wh;
        const int k1 = k0 + 1;
        float v0 = (k0 < 13) ? W1[k0 * 128 + n] : ((k0 == 13) ? b1[n] : 0.0f);
        float v1 = (k1 < 13) ? W1[k1 * 128 + n] : ((k1 == 13) ? b1[n] : 0.0f);
        W1f2[idx] = h2u(__floats2half2_rn(v0, v1));
    }
    if (tid < 128) b2s[tid] = b2[tid];
    __syncthreads();

    const u32* bcombo = Bf + combo2 * BF_STRIDE;
    float* mybuf = stgbuf + w * STG_WARP;
    u64*   fbuf  = (u64*)mybuf;           // feature table (lifetime-disjoint reuse)
    const int colblk = (l & 7) * 4;       // epilogue drain column block
    const int rsub   = l >> 3;            // epilogue drain row sub-index

    for (int t = blockIdx.x; t < NT2; t += GRID) {
        const int i  = t >> 2;
        const int j0 = (t & 3) << 8;            // 256-row tile
        const int jwarp = j0 + w * 32;          // warp's first row

        // ---- phase 1a: ONE row of pair features per lane -> packed hi/lo table ----
        {
            const float4 Bi = __ldg((const float4*)boxes + i);
            const float4 Bj = __ldg((const float4*)boxes + (jwarp + l));
            const float xi = Bi.x, yi = Bi.y, wi = Bi.z, hi_ = Bi.w;
            const float xj = Bj.x, yj = Bj.y, wj = Bj.z, hj = Bj.w;
            const float rwi = 1.0f / wi, rhi = 1.0f / hi_;
            const float dx = (xj - xi) * rwi;
            const float dy = (yj - yi) * rhi;
            const float dw = __logf(wj * rwi + 1e-6f);
            const float dh = __logf(hj * rhi + 1e-6f);
            const float iw = fmaxf(0.0f, fminf(xi + wi, xj + wj) - fmaxf(xi, xj));
            const float ih = fmaxf(0.0f, fminf(yi + hi_, yj + hj) - fmaxf(yi, yj));
            const float inter = iw * ih;
            const float uni   = wi * hi_ + wj * hj - inter;
            const float iou   = inter / (uni + 1e-6f);

            const float2 pr[7] = {
                {dx, dy}, {dw, dh}, {wi, hi_}, {wj, hj},
                {iou, xi}, {yi, xj}, {yj, 1.0f}
            };
            #pragma unroll
            for (int p = 0; p < 7; p++) {
                const __half2 hh = __floats2half2_rn(pr[p].x, pr[p].y);
                const float2 hf = __half22float2(hh);
                const __half2 ll = __floats2half2_rn(pr[p].x - hf.x, pr[p].y - hf.y);
                fbuf[l * FF_ROW + p] = (u64)h2u(hh) | ((u64)h2u(ll) << 32);
            }
        }
        __syncwarp();

        // ---- phase 1b: gather A-fragments (8 LDS.64) ----
        u32 fh[2][4], fl[2][4];
        #pragma unroll
        for (int s = 0; s < 2; s++) {
            const int r0 = npos + 16 * s;
            u64 v;
            v = fbuf[r0 * FF_ROW + lp];
            fh[s][0] = (u32)v; fl[s][0] = (u32)(v >> 32);
            v = fbuf[(r0 + 8) * FF_ROW + lp];
            fh[s][1] = (u32)v; fl[s][1] = (u32)(v >> 32);
            if (lp < 3) {
                v = fbuf[r0 * FF_ROW + lp + 4];
                fh[s][2] = (u32)v; fl[s][2] = (u32)(v >> 32);
                v = fbuf[(r0 + 8) * FF_ROW + lp + 4];
                fh[s][3] = (u32)v; fl[s][3] = (u32)(v >> 32);
            } else {
                fh[s][2] = 0; fl[s][2] = 0;
                fh[s][3] = 0; fl[s][3] = 0;
            }
        }
        __syncwarp();

        // ---- phase 1c: GEMM1 on tensor cores, fused ReLU+pack ----
        u32 hL[2][16], hH[2][16];
        #pragma unroll
        for (int gp = 0; gp < 8; gp++) {
            const uint4 wq = *(const uint4*)&W1f2[gp * 128 + 4 * l];
            #pragma unroll
            for (int s = 0; s < 2; s++) {
                float c[4] = {0.f, 0.f, 0.f, 0.f};
                mma16816(c, fh[s][0], fh[s][1], fh[s][2], fh[s][3], wq.x, wq.y);
                mma16816(c, fl[s][0], fl[s][1], fl[s][2], fl[s][3], wq.x, wq.y);
                hL[s][2 * gp]     = hmax2z(h2u(__floats2half2_rn(c[0], c[1])));
                hH[s][2 * gp]     = hmax2z(h2u(__floats2half2_rn(c[2], c[3])));
                float d[4] = {0.f, 0.f, 0.f, 0.f};
                mma16816(d, fh[s][0], fh[s][1], fh[s][2], fh[s][3], wq.z, wq.w);
                mma16816(d, fl[s][0], fl[s][1], fl[s][2], fl[s][3], wq.z, wq.w);
                hL[s][2 * gp + 1] = hmax2z(h2u(__floats2half2_rn(d[0], d[1])));
                hH[s][2 * gp + 1] = hmax2z(h2u(__floats2half2_rn(d[2], d[3])));
            }
        }

        // ---- epilogue addressing: fast path unless diagonal in this warp ----
        const int jd = i - jwarp;
        const bool hasdiag = (jd >= 0) && (jd < 32);
        const int jr0 = jwarp + rsub;
        const int orow0 = i * 1023 + jr0 - ((jr0 > i) ? 1 : 0);
        float* const dbase = out + (size_t)orow0 * 128 + colblk;

        // ---- phase 2: GEMM2 via HMMA, 4 passes of 32 cols; staged epilogue ----
        #pragma unroll
        for (int pass = 0; pass < 4; pass++) {
            float acc[2][4][4];
            #pragma unroll
            for (int s = 0; s < 2; s++)
                #pragma unroll
                for (int nt = 0; nt < 4; nt++) {
                    acc[s][nt][0] = 0.f; acc[s][nt][1] = 0.f;
                    acc[s][nt][2] = 0.f; acc[s][nt][3] = 0.f;
                }

            const u32* bp = bcombo + pass * 64;
            #pragma unroll
            for (int kt = 0; kt < 8; kt++) {
                const uint4 q0 = *(const uint4*)(bp + kt * 8);      // bv0 nt=0..3
                const uint4 q1 = *(const uint4*)(bp + kt * 8 + 4);  // bv1 nt=0..3
                #pragma unroll
                for (int s = 0; s < 2; s++) {
                    const u32 a0 = hL[s][2 * kt],     a1 = hH[s][2 * kt];
                    const u32 a2 = hL[s][2 * kt + 1], a3 = hH[s][2 * kt + 1];
                    mma16816(acc[s][0], a0, a1, a2, a3, q0.x, q1.x);
                    mma16816(acc[s][1], a0, a1, a2, a3, q0.y, q1.y);
                    mma16816(acc[s][2], a0, a1, a2, a3, q0.z, q1.z);
                    mma16816(acc[s][3], a0, a1, a2, a3, q0.w, q1.w);
                }
            }

            // stage: warp-private buffer, conflict-free STS.64 (row stride 40)
            #pragma unroll
            for (int s = 0; s < 2; s++)
                #pragma unroll
                for (int nt = 0; nt < 4; nt++) {
                    const int colo = nt * 8 + lp * 2;
                    float2 vL = make_float2(acc[s][nt][0], acc[s][nt][1]);
                    float2 vH = make_float2(acc[s][nt][2], acc[s][nt][3]);
                    *(float2*)&mybuf[((2 * s)     * 8 + npos) * STG_ROW + colo] = vL;
                    *(float2*)&mybuf[((2 * s + 1) * 8 + npos) * STG_ROW + colo] = vH;
                }
            __syncwarp();

            // drain: 8 x (LDS.128 + STG.128), full 128B lines, hoisted addressing
            const float4 bb = *(const float4*)&b2s[pass * 32 + colblk];
            if (!hasdiag) {
                float* dp = dbase + pass * 32;
                #pragma unroll
                for (int tt = 0; tt < 8; tt++) {
                    float4 v = *(const float4*)&mybuf[(4 * tt + rsub) * STG_ROW + colblk];
                    v.x += bb.x; v.y += bb.y; v.z += bb.z; v.w += bb.w;
                    *(float4*)(dp + tt * 512) = v;
                }
            } else {
                #pragma unroll
                for (int tt = 0; tt < 8; tt++) {
                    const int r = 4 * tt + rsub;
                    const int j = jwarp + r;
                    if (j != i) {
                        float4 v = *(const float4*)&mybuf[r * STG_ROW + colblk];
                        v.x += bb.x; v.y += bb.y; v.z += bb.z; v.w += bb.w;
                        const int outrow = i * 1023 + j - ((j > i) ? 1 : 0);
                        *(float4*)(out + (size_t)outrow * 128 + pass * 32 + colblk) = v;
                    }
                }
            }
            __syncwarp();
        }
    }
}

extern "C" void kernel_launch(void* const* d_in, const int* in_sizes, int n_in,
                              void* d_out, int out_size)
{
    const float* boxes = (const float*)d_in[0];
    const float* W1    = (const float*)d_in[1];
    const float* b1    = (const float*)d_in[2];
    const float* W2    = (const float*)d_in[3];
    const float* b2    = (const float*)d_in[4];
    float* out = (float*)d_out;

    cudaFuncSetAttribute(pair_mlp_hmma5,
                         cudaFuncAttributeMaxDynamicSharedMemorySize, SMEM_BYTES);
    pair_mlp_hmma5<<<GRID, 256, SMEM_BYTES>>>(boxes, W1, b1, W2, b2, out);
}

// round 15
// speedup vs baseline: 6.1743x; 1.0326x over previous
#include <cuda_runtime.h>
#include <cuda_fp16.h>
#include <cstring>

typedef unsigned long long u64;
typedef unsigned int u32;

#define KBOX   1024
#define NT2    4096          // 4096 tiles of 256 rows
#define GRID   304           // 152 SMs x 2 CTA/SM (GB300)
#define BF_STRIDE 260        // u32 per combo (64 chunks + 1 pad chunk)

// dynamic smem layout (bytes)
#define OFF_BF   0           // 32*260*4 = 33280
#define OFF_W1F  33280       // 4096
#define OFF_B2F  37376       // 4096 (b2 fragment table [pass][combo2][8])
#define OFF_STG  41472       // 8 warps * 1280 floats * 4 = 40960
#define SMEM_BYTES 82432
#define STG_WARP 1280        // floats per warp buffer (32 rows * 40)
#define STG_ROW  40          // floats per staged row (conflict-free padding)
#define FF_ROW   9           // u64 per feature row (7 pairs + pad, conflict-free)

__device__ __forceinline__ u32 h2u(__half2 h) {
    u32 u; memcpy(&u, &h, 4); return u;
}
__device__ __forceinline__ u32 hmax2z(u32 v) {
    __half2 h; memcpy(&h, &v, 4);
    h = __hmax2(h, __half2half2(__ushort_as_half(0)));
    return h2u(h);
}

// m16n8k16 fp16 MMA, fp32 accum
__device__ __forceinline__ void mma16816(float* c, u32 a0, u32 a1, u32 a2, u32 a3,
                                         u32 b0, u32 b1) {
    asm volatile(
        "mma.sync.aligned.m16n8k16.row.col.f32.f16.f16.f32 "
        "{%0,%1,%2,%3}, {%4,%5,%6,%7}, {%8,%9}, {%0,%1,%2,%3};"
        : "+f"(c[0]), "+f"(c[1]), "+f"(c[2]), "+f"(c[3])
        : "r"(a0), "r"(a1), "r"(a2), "r"(a3), "r"(b0), "r"(b1));
}

extern "C" __global__ void __launch_bounds__(256, 2)
pair_mlp_hmma6(const float* __restrict__ boxes,
               const float* __restrict__ W1, const float* __restrict__ b1,
               const float* __restrict__ W2, const float* __restrict__ b2,
               float* __restrict__ out)
{
    extern __shared__ char smemraw[];
    u32*   Bf   = (u32*)(smemraw + OFF_BF);    // fragment-ordered W2
    u32*   W1f2 = (u32*)(smemraw + OFF_W1F);   // pair-fragment-ordered W1 (+bias)
    float* b2f  = (float*)(smemraw + OFF_B2F); // b2 fragment table
    float* stgbuf = (float*)(smemraw + OFF_STG);

    const int tid = threadIdx.x;
    const int w   = tid >> 5;
    const int l   = tid & 31;
    const int lp  = l & 3;           // k-pair group within fragment
    const int npos = l >> 2;         // n position within fragment
    const int combo2 = npos * 4 + lp;

    // ---- one-time setup ----
    // W2 fragment pack
    for (int idx = tid; idx < 8192; idx += 256) {
        const int cb  = idx >> 8;
        const int rest = idx & 255;
        const int s2  = rest >> 3;
        const int q   = rest & 7;
        const int c   = q >> 2;
        const int wd  = q & 3;
        const int pass = s2 >> 3, kt = s2 & 7;
        const int lp_  = cb & 3,  np_ = cb >> 2;
        const int kp  = 8 * kt + lp_ + 4 * c;
        const int n   = pass * 32 + wd * 8 + np_;
        const __half2 p = __floats2half2_rn(W2[(2 * kp) * 128 + n],
                                            W2[(2 * kp + 1) * 128 + n]);
        Bf[cb * BF_STRIDE + s2 * 8 + q] = h2u(p);
    }
    // W1 pack for LDS.128: [gp][lane][4] = {g=2gp:b0,b1, g=2gp+1:b0,b1}
    for (int idx = tid; idx < 1024; idx += 256) {
        const int gp = idx >> 7;
        const int rest = idx & 127;
        const int ll = rest >> 2;
        const int q  = rest & 3;
        const int g  = 2 * gp + (q >> 1);
        const int wh = q & 1;
        const int n  = 8 * g + (ll >> 2);
        const int k0 = 2 * (ll & 3) + 8 * wh;
        const int k1 = k0 + 1;
        float v0 = (k0 < 13) ? W1[k0 * 128 + n] : ((k0 == 13) ? b1[n] : 0.0f);
        float v1 = (k1 < 13) ? W1[k1 * 128 + n] : ((k1 == 13) ? b1[n] : 0.0f);
        W1f2[idx] = h2u(__floats2half2_rn(v0, v1));
    }
    // b2 fragment table: b2f[pass][combo2][2*nt+t] = b2[pass*32 + nt*8 + lp*2 + t]
    for (int idx = tid; idx < 1024; idx += 256) {
        const int pass = idx >> 8;
        const int rest = idx & 255;
        const int cb   = rest >> 3;
        const int k    = rest & 7;
        const int nt   = k >> 1;
        const int tt   = k & 1;
        const int lp_  = cb & 3;
        b2f[idx] = b2[pass * 32 + nt * 8 + lp_ * 2 + tt];
    }
    __syncthreads();

    const u32* bcombo = Bf + combo2 * BF_STRIDE;
    float* mybuf = stgbuf + w * STG_WARP;
    uint2* fbuf  = (uint2*)mybuf;         // feature table (lifetime-disjoint reuse)
    const float* myb2f = b2f + combo2 * 8;
    const int colblk = (l & 7) * 4;       // epilogue drain column block
    const int rsub   = l >> 3;            // epilogue drain row sub-index

    for (int t = blockIdx.x; t < NT2; t += GRID) {
        const int i  = t >> 2;
        const int j0 = (t & 3) << 8;            // 256-row tile
        const int jwarp = j0 + w * 32;          // warp's first row

        // ---- phase 1a: ONE row of pair features per lane -> packed hi/lo table ----
        {
            const float4 Bi = __ldg((const float4*)boxes + i);
            const float4 Bj = __ldg((const float4*)boxes + (jwarp + l));
            const float xi = Bi.x, yi = Bi.y, wi = Bi.z, hi_ = Bi.w;
            const float xj = Bj.x, yj = Bj.y, wj = Bj.z, hj = Bj.w;
            const float rwi = 1.0f / wi, rhi = 1.0f / hi_;
            const float dx = (xj - xi) * rwi;
            const float dy = (yj - yi) * rhi;
            const float dw = __logf(wj * rwi + 1e-6f);
            const float dh = __logf(hj * rhi + 1e-6f);
            const float iw = fmaxf(0.0f, fminf(xi + wi, xj + wj) - fmaxf(xi, xj));
            const float ih = fmaxf(0.0f, fminf(yi + hi_, yj + hj) - fmaxf(yi, yj));
            const float inter = iw * ih;
            const float uni   = wi * hi_ + wj * hj - inter;
            const float iou   = inter / (uni + 1e-6f);

            const float2 pr[7] = {
                {dx, dy}, {dw, dh}, {wi, hi_}, {wj, hj},
                {iou, xi}, {yi, xj}, {yj, 1.0f}
            };
            #pragma unroll
            for (int p = 0; p < 7; p++) {
                const __half2 hh = __floats2half2_rn(pr[p].x, pr[p].y);
                const float2 hf = __half22float2(hh);
                const __half2 ll = __floats2half2_rn(pr[p].x - hf.x, pr[p].y - hf.y);
                fbuf[l * FF_ROW + p] = make_uint2(h2u(hh), h2u(ll));
            }
        }
        __syncwarp();

        // ---- phase 1b: gather A-fragments (8 LDS.64) ----
        u32 fh[2][4], fl[2][4];
        #pragma unroll
        for (int s = 0; s < 2; s++) {
            const int r0 = npos + 16 * s;
            uint2 v;
            v = fbuf[r0 * FF_ROW + lp];
            fh[s][0] = v.x; fl[s][0] = v.y;
            v = fbuf[(r0 + 8) * FF_ROW + lp];
            fh[s][1] = v.x; fl[s][1] = v.y;
            if (lp < 3) {
                v = fbuf[r0 * FF_ROW + lp + 4];
                fh[s][2] = v.x; fl[s][2] = v.y;
                v = fbuf[(r0 + 8) * FF_ROW + lp + 4];
                fh[s][3] = v.x; fl[s][3] = v.y;
            } else {
                fh[s][2] = 0; fl[s][2] = 0;
                fh[s][3] = 0; fl[s][3] = 0;
            }
        }
        __syncwarp();

        // ---- phase 1c: GEMM1 on tensor cores, fused ReLU+pack ----
        u32 hL[2][16], hH[2][16];
        #pragma unroll
        for (int gp = 0; gp < 8; gp++) {
            const uint4 wq = *(const uint4*)&W1f2[gp * 128 + 4 * l];
            #pragma unroll
            for (int s = 0; s < 2; s++) {
                float c[4] = {0.f, 0.f, 0.f, 0.f};
                mma16816(c, fh[s][0], fh[s][1], fh[s][2], fh[s][3], wq.x, wq.y);
                mma16816(c, fl[s][0], fl[s][1], fl[s][2], fl[s][3], wq.x, wq.y);
                hL[s][2 * gp]     = hmax2z(h2u(__floats2half2_rn(c[0], c[1])));
                hH[s][2 * gp]     = hmax2z(h2u(__floats2half2_rn(c[2], c[3])));
                float d[4] = {0.f, 0.f, 0.f, 0.f};
                mma16816(d, fh[s][0], fh[s][1], fh[s][2], fh[s][3], wq.z, wq.w);
                mma16816(d, fl[s][0], fl[s][1], fl[s][2], fl[s][3], wq.z, wq.w);
                hL[s][2 * gp + 1] = hmax2z(h2u(__floats2half2_rn(d[0], d[1])));
                hH[s][2 * gp + 1] = hmax2z(h2u(__floats2half2_rn(d[2], d[3])));
            }
        }

        // ---- epilogue addressing: fast path unless diagonal in this warp ----
        const int jd = i - jwarp;
        const bool hasdiag = (jd >= 0) && (jd < 32);
        const int jr0 = jwarp + rsub;
        const int orow0 = i * 1023 + jr0 - ((jr0 > i) ? 1 : 0);
        float* const dbase = out + (size_t)orow0 * 128 + colblk;

        // ---- phase 2: GEMM2 via HMMA, 4 passes of 32 cols; staged epilogue ----
        #pragma unroll
        for (int pass = 0; pass < 4; pass++) {
            // acc init = b2 fragments (bias folded into accumulators)
            const float4 i0 = *(const float4*)(myb2f + pass * 256);
            const float4 i1 = *(const float4*)(myb2f + pass * 256 + 4);
            float acc[2][4][4];
            #pragma unroll
            for (int s = 0; s < 2; s++) {
                acc[s][0][0] = i0.x; acc[s][0][1] = i0.y;
                acc[s][0][2] = i0.x; acc[s][0][3] = i0.y;
                acc[s][1][0] = i0.z; acc[s][1][1] = i0.w;
                acc[s][1][2] = i0.z; acc[s][1][3] = i0.w;
                acc[s][2][0] = i1.x; acc[s][2][1] = i1.y;
                acc[s][2][2] = i1.x; acc[s][2][3] = i1.y;
                acc[s][3][0] = i1.z; acc[s][3][1] = i1.w;
                acc[s][3][2] = i1.z; acc[s][3][3] = i1.w;
            }

            const u32* bp = bcombo + pass * 64;
            #pragma unroll
            for (int kt = 0; kt < 8; kt++) {
                const uint4 q0 = *(const uint4*)(bp + kt * 8);      // bv0 nt=0..3
                const uint4 q1 = *(const uint4*)(bp + kt * 8 + 4);  // bv1 nt=0..3
                #pragma unroll
                for (int s = 0; s < 2; s++) {
                    const u32 a0 = hL[s][2 * kt],     a1 = hH[s][2 * kt];
                    const u32 a2 = hL[s][2 * kt + 1], a3 = hH[s][2 * kt + 1];
                    mma16816(acc[s][0], a0, a1, a2, a3, q0.x, q1.x);
                    mma16816(acc[s][1], a0, a1, a2, a3, q0.y, q1.y);
                    mma16816(acc[s][2], a0, a1, a2, a3, q0.z, q1.z);
                    mma16816(acc[s][3], a0, a1, a2, a3, q0.w, q1.w);
                }
            }

            // stage: warp-private buffer, conflict-free STS.64 (row stride 40)
            #pragma unroll
            for (int s = 0; s < 2; s++)
                #pragma unroll
                for (int nt = 0; nt < 4; nt++) {
                    const int colo = nt * 8 + lp * 2;
                    float2 vL = make_float2(acc[s][nt][0], acc[s][nt][1]);
                    float2 vH = make_float2(acc[s][nt][2], acc[s][nt][3]);
                    *(float2*)&mybuf[((2 * s)     * 8 + npos) * STG_ROW + colo] = vL;
                    *(float2*)&mybuf[((2 * s + 1) * 8 + npos) * STG_ROW + colo] = vH;
                }
            __syncwarp();

            // drain: 8 x (LDS.128 + STG.128), full 128B lines, hoisted addressing
            if (!hasdiag) {
                float* dp = dbase + pass * 32;
                #pragma unroll
                for (int tt = 0; tt < 8; tt++) {
                    float4 v = *(const float4*)&mybuf[(4 * tt + rsub) * STG_ROW + colblk];
                    *(float4*)(dp + tt * 512) = v;
                }
            } else {
                #pragma unroll
                for (int tt = 0; tt < 8; tt++) {
                    const int r = 4 * tt + rsub;
                    const int j = jwarp + r;
                    if (j != i) {
                        float4 v = *(const float4*)&mybuf[r * STG_ROW + colblk];
                        const int outrow = i * 1023 + j - ((j > i) ? 1 : 0);
                        *(float4*)(out + (size_t)outrow * 128 + pass * 32 + colblk) = v;
                    }
                }
            }
            __syncwarp();
        }
    }
}

extern "C" void kernel_launch(void* const* d_in, const int* in_sizes, int n_in,
                              void* d_out, int out_size)
{
    const float* boxes = (const float*)d_in[0];
    const float* W1    = (const float*)d_in[1];
    const float* b1    = (const float*)d_in[2];
    const float* W2    = (const float*)d_in[3];
    const float* b2    = (const float*)d_in[4];
    float* out = (float*)d_out;

    cudaFuncSetAttribute(pair_mlp_hmma6,
                         cudaFuncAttributeMaxDynamicSharedMemorySize, SMEM_BYTES);
    pair_mlp_hmma6<<<GRID, 256, SMEM_BYTES>>>(boxes, W1, b1, W2, b2, out);
}

// round 16
// speedup vs baseline: 6.2591x; 1.0137x over previous
#include <cuda_runtime.h>
#include <cuda_fp16.h>
#include <cstring>

typedef unsigned long long u64;
typedef unsigned int u32;

#define KBOX   1024
#define NT2    4096          // 4096 tiles of 256 rows
#define GRID   304           // 152 SMs x 2 CTA/SM (GB300)
#define BF_STRIDE 260        // u32 per combo (64 chunks + 1 pad chunk)

// dynamic smem layout (bytes)
#define OFF_BF   0           // 32*260*4 = 33280
#define OFF_W1F  33280       // 4096
#define OFF_B2F  37376       // 4096 (b2 fragment table [pass][combo2][8])
#define OFF_FF   41472       // 8 warps * 288 uint2 = 18432 (feature tables)
#define OFF_STG  59904       // 8 warps * 1280 floats * 4 = 40960
#define SMEM_BYTES 100864
#define STG_WARP 1280        // floats per warp buffer (32 rows * 40)
#define STG_ROW  40          // floats per staged row (conflict-free padding)
#define FF_ROW   9           // uint2 per feature row (7 pairs + pad)
#define FF_WARP  (32 * FF_ROW)

__device__ __forceinline__ u32 h2u(__half2 h) {
    u32 u; memcpy(&u, &h, 4); return u;
}
__device__ __forceinline__ u32 hmax2z(u32 v) {
    __half2 h; memcpy(&h, &v, 4);
    h = __hmax2(h, __half2half2(__ushort_as_half(0)));
    return h2u(h);
}

// m16n8k16 fp16 MMA, fp32 accum
__device__ __forceinline__ void mma16816(float* c, u32 a0, u32 a1, u32 a2, u32 a3,
                                         u32 b0, u32 b1) {
    asm volatile(
        "mma.sync.aligned.m16n8k16.row.col.f32.f16.f16.f32 "
        "{%0,%1,%2,%3}, {%4,%5,%6,%7}, {%8,%9}, {%0,%1,%2,%3};"
        : "+f"(c[0]), "+f"(c[1]), "+f"(c[2]), "+f"(c[3])
        : "r"(a0), "r"(a1), "r"(a2), "r"(a3), "r"(b0), "r"(b1));
}

extern "C" __global__ void __launch_bounds__(256, 2)
pair_mlp_hmma7(const float* __restrict__ boxes,
               const float* __restrict__ W1, const float* __restrict__ b1,
               const float* __restrict__ W2, const float* __restrict__ b2,
               float* __restrict__ out)
{
    extern __shared__ char smemraw[];
    u32*   Bf   = (u32*)(smemraw + OFF_BF);    // fragment-ordered W2
    u32*   W1f2 = (u32*)(smemraw + OFF_W1F);   // pair-fragment-ordered W1 (+bias)
    float* b2f  = (float*)(smemraw + OFF_B2F); // b2 fragment table
    uint2* ffbuf = (uint2*)(smemraw + OFF_FF); // per-warp feature tables
    float* stgbuf = (float*)(smemraw + OFF_STG);

    const int tid = threadIdx.x;
    const int w   = tid >> 5;
    const int l   = tid & 31;
    const int lp  = l & 3;           // k-pair group within fragment
    const int npos = l >> 2;         // n position within fragment
    const int combo2 = npos * 4 + lp;

    // ---- one-time setup ----
    // W2 fragment pack
    for (int idx = tid; idx < 8192; idx += 256) {
        const int cb  = idx >> 8;
        const int rest = idx & 255;
        const int s2  = rest >> 3;
        const int q   = rest & 7;
        const int c   = q >> 2;
        const int wd  = q & 3;
        const int pass = s2 >> 3, kt = s2 & 7;
        const int lp_  = cb & 3,  np_ = cb >> 2;
        const int kp  = 8 * kt + lp_ + 4 * c;
        const int n   = pass * 32 + wd * 8 + np_;
        const __half2 p = __floats2half2_rn(W2[(2 * kp) * 128 + n],
                                            W2[(2 * kp + 1) * 128 + n]);
        Bf[cb * BF_STRIDE + s2 * 8 + q] = h2u(p);
    }
    // W1 pack for LDS.128: [gp][lane][4] = {g=2gp:b0,b1, g=2gp+1:b0,b1}
    for (int idx = tid; idx < 1024; idx += 256) {
        const int gp = idx >> 7;
        const int rest = idx & 127;
        const int ll = rest >> 2;
        const int q  = rest & 3;
        const int g  = 2 * gp + (q >> 1);
        const int wh = q & 1;
        const int n  = 8 * g + (ll >> 2);
        const int k0 = 2 * (ll & 3) + 8 * wh;
        const int k1 = k0 + 1;
        float v0 = (k0 < 13) ? W1[k0 * 128 + n] : ((k0 == 13) ? b1[n] : 0.0f);
        float v1 = (k1 < 13) ? W1[k1 * 128 + n] : ((k1 == 13) ? b1[n] : 0.0f);
        W1f2[idx] = h2u(__floats2half2_rn(v0, v1));
    }
    // b2 fragment table
    for (int idx = tid; idx < 1024; idx += 256) {
        const int pass = idx >> 8;
        const int rest = idx & 255;
        const int cb   = rest >> 3;
        const int k    = rest & 7;
        const int nt   = k >> 1;
        const int tt   = k & 1;
        const int lp_  = cb & 3;
        b2f[idx] = b2[pass * 32 + nt * 8 + lp_ * 2 + tt];
    }
    __syncthreads();

    const u32* bcombo = Bf + combo2 * BF_STRIDE;
    float* mybuf = stgbuf + w * STG_WARP;
    uint2* myff  = ffbuf + w * FF_WARP;
    const float* myb2f = b2f + combo2 * 8;
    const int colblk = (l & 7) * 4;       // epilogue drain column block
    const int rsub   = l >> 3;            // epilogue drain row sub-index

    // ---- phase 1a as a macro: pair features for one row per lane -> table ----
#define PHASE1A(T2) do {                                                        \
        const int i2  = (T2) >> 2;                                              \
        const int jw2 = (((T2) & 3) << 8) + w * 32;                             \
        const float4 Bi = __ldg((const float4*)boxes + i2);                     \
        const float4 Bj = __ldg((const float4*)boxes + (jw2 + l));              \
        const float xi = Bi.x, yi = Bi.y, wi = Bi.z, hi_ = Bi.w;                \
        const float xj = Bj.x, yj = Bj.y, wj = Bj.z, hj = Bj.w;                 \
        const float rwi = 1.0f / wi, rhi = 1.0f / hi_;                          \
        const float dx = (xj - xi) * rwi;                                       \
        const float dy = (yj - yi) * rhi;                                       \
        const float dw = __logf(wj * rwi + 1e-6f);                              \
        const float dh = __logf(hj * rhi + 1e-6f);                              \
        const float iw = fmaxf(0.0f, fminf(xi + wi, xj + wj) - fmaxf(xi, xj));  \
        const float ih = fmaxf(0.0f, fminf(yi + hi_, yj + hj) - fmaxf(yi, yj)); \
        const float inter = iw * ih;                                            \
        const float uni   = wi * hi_ + wj * hj - inter;                         \
        const float iou   = inter / (uni + 1e-6f);                              \
        const float2 pr[7] = {                                                  \
            {dx, dy}, {dw, dh}, {wi, hi_}, {wj, hj},                            \
            {iou, xi}, {yi, xj}, {yj, 1.0f}                                     \
        };                                                                      \
        _Pragma("unroll")                                                       \
        for (int p = 0; p < 7; p++) {                                           \
            const __half2 hh = __floats2half2_rn(pr[p].x, pr[p].y);             \
            const float2 hf = __half22float2(hh);                               \
            const __half2 ll2 = __floats2half2_rn(pr[p].x - hf.x, pr[p].y - hf.y); \
            myff[l * FF_ROW + p] = make_uint2(h2u(hh), h2u(ll2));               \
        }                                                                       \
    } while (0)

    // prologue: features for first tile
    PHASE1A(blockIdx.x);
    __syncwarp();

    for (int t = blockIdx.x; t < NT2; t += GRID) {
        const int i  = t >> 2;
        const int jwarp = ((t & 3) << 8) + w * 32;

        // ---- phase 1b: gather A-fragments (8 LDS.64) ----
        u32 fh[2][4], fl[2][4];
        #pragma unroll
        for (int s = 0; s < 2; s++) {
            const int r0 = npos + 16 * s;
            uint2 v;
            v = myff[r0 * FF_ROW + lp];
            fh[s][0] = v.x; fl[s][0] = v.y;
            v = myff[(r0 + 8) * FF_ROW + lp];
            fh[s][1] = v.x; fl[s][1] = v.y;
            if (lp < 3) {
                v = myff[r0 * FF_ROW + lp + 4];
                fh[s][2] = v.x; fl[s][2] = v.y;
                v = myff[(r0 + 8) * FF_ROW + lp + 4];
                fh[s][3] = v.x; fl[s][3] = v.y;
            } else {
                fh[s][2] = 0; fl[s][2] = 0;
                fh[s][3] = 0; fl[s][3] = 0;
            }
        }

        // ---- phase 1c: GEMM1 on tensor cores, fused ReLU+pack ----
        u32 hL[2][16], hH[2][16];
        #pragma unroll
        for (int gp = 0; gp < 8; gp++) {
            const uint4 wq = *(const uint4*)&W1f2[gp * 128 + 4 * l];
            #pragma unroll
            for (int s = 0; s < 2; s++) {
                float c[4] = {0.f, 0.f, 0.f, 0.f};
                mma16816(c, fh[s][0], fh[s][1], fh[s][2], fh[s][3], wq.x, wq.y);
                mma16816(c, fl[s][0], fl[s][1], fl[s][2], fl[s][3], wq.x, wq.y);
                hL[s][2 * gp]     = hmax2z(h2u(__floats2half2_rn(c[0], c[1])));
                hH[s][2 * gp]     = hmax2z(h2u(__floats2half2_rn(c[2], c[3])));
                float d[4] = {0.f, 0.f, 0.f, 0.f};
                mma16816(d, fh[s][0], fh[s][1], fh[s][2], fh[s][3], wq.z, wq.w);
                mma16816(d, fl[s][0], fl[s][1], fl[s][2], fl[s][3], wq.z, wq.w);
                hL[s][2 * gp + 1] = hmax2z(h2u(__floats2half2_rn(d[0], d[1])));
                hH[s][2 * gp + 1] = hmax2z(h2u(__floats2half2_rn(d[2], d[3])));
            }
        }

        // ---- pipelined phase 1a for tile t+GRID (overlaps phase 2's L1 work) ----
        if (t + GRID < NT2) {
            PHASE1A(t + GRID);
        }
        __syncwarp();   // publish feature table for next iteration's 1b

        // ---- epilogue addressing: fast path unless diagonal in this warp ----
        const int jd = i - jwarp;
        const bool hasdiag = (jd >= 0) && (jd < 32);
        const int jr0 = jwarp + rsub;
        const int orow0 = i * 1023 + jr0 - ((jr0 > i) ? 1 : 0);
        float* const dbase = out + (size_t)orow0 * 128 + colblk;

        // ---- phase 2: GEMM2 via HMMA, 4 passes of 32 cols; staged epilogue ----
        #pragma unroll
        for (int pass = 0; pass < 4; pass++) {
            // acc init = b2 fragments (bias folded into accumulators)
            const float4 i0 = *(const float4*)(myb2f + pass * 256);
            const float4 i1 = *(const float4*)(myb2f + pass * 256 + 4);
            float acc[2][4][4];
            #pragma unroll
            for (int s = 0; s < 2; s++) {
                acc[s][0][0] = i0.x; acc[s][0][1] = i0.y;
                acc[s][0][2] = i0.x; acc[s][0][3] = i0.y;
                acc[s][1][0] = i0.z; acc[s][1][1] = i0.w;
                acc[s][1][2] = i0.z; acc[s][1][3] = i0.w;
                acc[s][2][0] = i1.x; acc[s][2][1] = i1.y;
                acc[s][2][2] = i1.x; acc[s][2][3] = i1.y;
                acc[s][3][0] = i1.z; acc[s][3][1] = i1.w;
                acc[s][3][2] = i1.z; acc[s][3][3] = i1.w;
            }

            const u32* bp = bcombo + pass * 64;
            #pragma unroll
            for (int kt = 0; kt < 8; kt++) {
                const uint4 q0 = *(const uint4*)(bp + kt * 8);      // bv0 nt=0..3
                const uint4 q1 = *(const uint4*)(bp + kt * 8 + 4);  // bv1 nt=0..3
                #pragma unroll
                for (int s = 0; s < 2; s++) {
                    const u32 a0 = hL[s][2 * kt],     a1 = hH[s][2 * kt];
                    const u32 a2 = hL[s][2 * kt + 1], a3 = hH[s][2 * kt + 1];
                    mma16816(acc[s][0], a0, a1, a2, a3, q0.x, q1.x);
                    mma16816(acc[s][1], a0, a1, a2, a3, q0.y, q1.y);
                    mma16816(acc[s][2], a0, a1, a2, a3, q0.z, q1.z);
                    mma16816(acc[s][3], a0, a1, a2, a3, q0.w, q1.w);
                }
            }

            // stage: warp-private buffer, conflict-free STS.64 (row stride 40)
            #pragma unroll
            for (int s = 0; s < 2; s++)
                #pragma unroll
                for (int nt = 0; nt < 4; nt++) {
                    const int colo = nt * 8 + lp * 2;
                    float2 vL = make_float2(acc[s][nt][0], acc[s][nt][1]);
                    float2 vH = make_float2(acc[s][nt][2], acc[s][nt][3]);
                    *(float2*)&mybuf[((2 * s)     * 8 + npos) * STG_ROW + colo] = vL;
                    *(float2*)&mybuf[((2 * s + 1) * 8 + npos) * STG_ROW + colo] = vH;
                }
            __syncwarp();

            // drain: 8 x (LDS.128 + streaming STG.128), full 128B lines
            if (!hasdiag) {
                float* dp = dbase + pass * 32;
                #pragma unroll
                for (int tt = 0; tt < 8; tt++) {
                    float4 v = *(const float4*)&mybuf[(4 * tt + rsub) * STG_ROW + colblk];
                    __stcs((float4*)(dp + tt * 512), v);
                }
            } else {
                #pragma unroll
                for (int tt = 0; tt < 8; tt++) {
                    const int r = 4 * tt + rsub;
                    const int j = jwarp + r;
                    if (j != i) {
                        float4 v = *(const float4*)&mybuf[r * STG_ROW + colblk];
                        const int outrow = i * 1023 + j - ((j > i) ? 1 : 0);
                        __stcs((float4*)(out + (size_t)outrow * 128 + pass * 32 + colblk), v);
                    }
                }
            }
            __syncwarp();
        }
    }
#undef PHASE1A
}

extern "C" void kernel_launch(void* const* d_in, const int* in_sizes, int n_in,
                              void* d_out, int out_size)
{
    const float* boxes = (const float*)d_in[0];
    const float* W1    = (const float*)d_in[1];
    const float* b1    = (const float*)d_in[2];
    const float* W2    = (const float*)d_in[3];
    const float* b2    = (const float*)d_in[4];
    float* out = (float*)d_out;

    cudaFuncSetAttribute(pair_mlp_hmma7,
                         cudaFuncAttributeMaxDynamicSharedMemorySize, SMEM_BYTES);
    pair_mlp_hmma7<<<GRID, 256, SMEM_BYTES>>>(boxes, W1, b1, W2, b2, out);
}